// round 2
// baseline (speedup 1.0000x reference)
#include <cuda_runtime.h>
#include <cuda_fp16.h>

#define BB_  2
#define SS_  2048
#define DD_  1024
#define HH_  16
#define HDIM 64

// Scratch: fp16 Q/K/V in [B, H, S, hd] layout (8 MB each), packed mask bits (1 MB)
__device__ __half g_Q[(size_t)BB_ * HH_ * SS_ * HDIM];
__device__ __half g_K[(size_t)BB_ * HH_ * SS_ * HDIM];
__device__ __half g_V[(size_t)BB_ * HH_ * SS_ * HDIM];
__device__ unsigned int g_mb[(size_t)BB_ * SS_ * SS_ / 32];

// ---------------------------------------------------------------------------
__device__ __forceinline__ void mma16816(float (&c)[4], const unsigned (&a)[4],
                                         const unsigned (&b)[2]) {
    asm volatile(
        "mma.sync.aligned.m16n8k16.row.col.f32.f16.f16.f32 "
        "{%0,%1,%2,%3}, {%4,%5,%6,%7}, {%8,%9}, {%0,%1,%2,%3};\n"
        : "+f"(c[0]), "+f"(c[1]), "+f"(c[2]), "+f"(c[3])
        : "r"(a[0]), "r"(a[1]), "r"(a[2]), "r"(a[3]), "r"(b[0]), "r"(b[1]));
}

__device__ __forceinline__ unsigned pack_h2(float lo, float hi) {
    __half2 h = __floats2half2_rn(lo, hi);
    return *reinterpret_cast<unsigned*>(&h);
}

__device__ __forceinline__ unsigned smem_u32(const void* p) {
    unsigned r;
    asm("{ .reg .u64 t; cvta.to.shared.u64 t, %1; cvt.u32.u64 %0, t; }"
        : "=r"(r) : "l"(p));
    return r;
}

#define CP_ASYNC16(dst, src) \
    asm volatile("cp.async.cg.shared.global [%0], [%1], 16;\n" ::"r"(dst), "l"(src))
#define CP_COMMIT() asm volatile("cp.async.commit_group;\n")
#define CP_WAIT(n)  asm volatile("cp.async.wait_group %0;\n" ::"n"(n))

__device__ __forceinline__ void ldsm_x2(unsigned& r0, unsigned& r1, unsigned addr) {
    asm volatile("ldmatrix.sync.aligned.m8n8.x2.shared.b16 {%0,%1}, [%2];"
                 : "=r"(r0), "=r"(r1) : "r"(addr));
}
__device__ __forceinline__ void ldsm_x2_t(unsigned& r0, unsigned& r1, unsigned addr) {
    asm volatile("ldmatrix.sync.aligned.m8n8.x2.trans.shared.b16 {%0,%1}, [%2];"
                 : "=r"(r0), "=r"(r1) : "r"(addr));
}

// ---------------------------------------------------------------------------
// Kernel 0: pack mask (int32, nonzero==keep) into bitmask
// ---------------------------------------------------------------------------
__global__ void pack_mask_kernel(const int* __restrict__ mask) {
    int idx = blockIdx.x * 256 + threadIdx.x;
    int m = mask[idx];
    unsigned bal = __ballot_sync(0xffffffffu, m != 0);
    if ((threadIdx.x & 31) == 0) g_mb[idx >> 5] = bal;
}

// ---------------------------------------------------------------------------
// Kernel 1: fused projection GEMMs (z = 0/1/2 -> Q/K/V).
// C[m,n] = sum_k X[m,k]*W[n,k] + bias[n], fp32 in, fp16 out to [B,H,S,hd].
// 128x128x32 tiles, cp.async double-buffered fp32 stages, convert at read.
// ---------------------------------------------------------------------------
#define PSTRIDE 36   // fp32 row stride in smem (144 B, 16B-aligned, conflict-free)
#define PSTAGE  (128 * PSTRIDE)

__global__ __launch_bounds__(256) void proj_kernel(
    const float* __restrict__ Xq, const float* __restrict__ Xk, const float* __restrict__ Xv,
    const float* __restrict__ Wq, const float* __restrict__ Wk, const float* __restrict__ Wv,
    const float* __restrict__ bq, const float* __restrict__ bk, const float* __restrict__ bv) {
    extern __shared__ float smemf[];
    float* sA = smemf;                 // [2][128*36]
    float* sB = smemf + 2 * PSTAGE;    // [2][128*36]

    const int z = blockIdx.z;
    const float* X = (z == 0) ? Xq : (z == 1) ? Xk : Xv;
    const float* W = (z == 0) ? Wq : (z == 1) ? Wk : Wv;
    const float* bias = (z == 0) ? bq : (z == 1) ? bk : bv;
    __half* out = (z == 0) ? g_Q : (z == 1) ? g_K : g_V;

    const int tid = threadIdx.x;
    const int warp = tid >> 5, lane = tid & 31;
    const int g = lane >> 2, t = lane & 3;
    const int wm = warp & 1, wn = warp >> 1;
    const int m0 = blockIdx.y * 128, n0 = blockIdx.x * 128;

    const unsigned sAu = smem_u32(sA), sBu = smem_u32(sB);
    const int crow = tid >> 3, c4 = tid & 7;   // base chunk coords (+32 rows per i)

    // stage loader: 4 chunks A + 4 chunks B per thread
    auto load_stage = [&](int buf, int kk) {
#pragma unroll
        for (int i = 0; i < 4; i++) {
            int row = crow + i * 32;
            unsigned dA = sAu + (unsigned)(buf * PSTAGE + row * PSTRIDE + c4 * 4) * 4u;
            CP_ASYNC16(dA, X + (size_t)(m0 + row) * DD_ + kk + c4 * 4);
            unsigned dB = sBu + (unsigned)(buf * PSTAGE + row * PSTRIDE + c4 * 4) * 4u;
            CP_ASYNC16(dB, W + (size_t)(n0 + row) * DD_ + kk + c4 * 4);
        }
        CP_COMMIT();
    };

    float acc[4][4][4];
#pragma unroll
    for (int mi = 0; mi < 4; mi++)
#pragma unroll
        for (int ni = 0; ni < 4; ni++)
#pragma unroll
            for (int j = 0; j < 4; j++) acc[mi][ni][j] = 0.f;

    load_stage(0, 0);

    const int NSTEPS = DD_ / 32;
    for (int s = 0; s < NSTEPS; s++) {
        if (s + 1 < NSTEPS) {
            load_stage((s + 1) & 1, (s + 1) * 32);
            CP_WAIT(1);
        } else {
            CP_WAIT(0);
        }
        __syncthreads();

        const float* bufA = sA + (s & 1) * PSTAGE;
        const float* bufB = sB + (s & 1) * PSTAGE;
#pragma unroll
        for (int k16 = 0; k16 < 32; k16 += 16) {
            unsigned a[4][4], b[4][2];
#pragma unroll
            for (int mi = 0; mi < 4; mi++) {
                const float* base = bufA + (wm * 64 + mi * 16 + g) * PSTRIDE + k16 + 2 * t;
                float2 v0 = *(const float2*)(base);
                float2 v1 = *(const float2*)(base + 8 * PSTRIDE);
                float2 v2 = *(const float2*)(base + 8);
                float2 v3 = *(const float2*)(base + 8 * PSTRIDE + 8);
                a[mi][0] = pack_h2(v0.x, v0.y);
                a[mi][1] = pack_h2(v1.x, v1.y);
                a[mi][2] = pack_h2(v2.x, v2.y);
                a[mi][3] = pack_h2(v3.x, v3.y);
            }
#pragma unroll
            for (int ni = 0; ni < 4; ni++) {
                const float* base = bufB + (wn * 32 + ni * 8 + g) * PSTRIDE + k16 + 2 * t;
                float2 v0 = *(const float2*)(base);
                float2 v1 = *(const float2*)(base + 8);
                b[ni][0] = pack_h2(v0.x, v0.y);
                b[ni][1] = pack_h2(v1.x, v1.y);
            }
#pragma unroll
            for (int mi = 0; mi < 4; mi++)
#pragma unroll
                for (int ni = 0; ni < 4; ni++) mma16816(acc[mi][ni], a[mi], b[ni]);
        }
        __syncthreads();
    }

    // Epilogue: add bias, convert to fp16, scatter into [B,H,S,hd]
#pragma unroll
    for (int mi = 0; mi < 4; mi++) {
        int mrow = m0 + wm * 64 + mi * 16 + g;
        int bidx = mrow >> 11;
        int s = mrow & (SS_ - 1);
#pragma unroll
        for (int ni = 0; ni < 4; ni++) {
            int ncol = n0 + wn * 32 + ni * 8 + 2 * t;
            float b0 = bias[ncol], b1 = bias[ncol + 1];
            int h = ncol >> 6, d = ncol & 63;
            size_t base = (((size_t)(bidx * HH_ + h) * SS_ + s) * HDIM + d);
            *(__half2*)(out + base) =
                __floats2half2_rn(acc[mi][ni][0] + b0, acc[mi][ni][1] + b1);
            *(__half2*)(out + base + 8 * HDIM) =
                __floats2half2_rn(acc[mi][ni][2] + b0, acc[mi][ni][3] + b1);
        }
    }
}

// ---------------------------------------------------------------------------
// Kernel 2: flash attention. Grid (S/128, B*H). 8 warps x 16 Q rows each.
// cp.async double-buffered KV tiles of 64, ldmatrix fragments (V via .trans).
// ---------------------------------------------------------------------------
#define ASTRIDE 72   // half stride (144 B)
#define ATILE   (64 * ASTRIDE)

__global__ __launch_bounds__(256) void attn_kernel(float* __restrict__ out) {
    __shared__ __align__(16) __half sK[2][ATILE];
    __shared__ __align__(16) __half sV[2][ATILE];

    const int tid = threadIdx.x;
    const int warp = tid >> 5, lane = tid & 31;
    const int g = lane >> 2, t = lane & 3;

    const int bh = blockIdx.y;
    const int bidx = bh >> 4, h = bh & 15;
    const int q0 = blockIdx.x * 128;
    const int qr = q0 + warp * 16 + g;

    // Q fragments in registers for the whole KV loop
    const __half* Qp = g_Q + ((size_t)bh * SS_ + q0 + warp * 16) * HDIM;
    unsigned qa[4][4];
#pragma unroll
    for (int kt = 0; kt < 4; kt++) {
        const __half* base = Qp + g * HDIM + kt * 16 + 2 * t;
        qa[kt][0] = *(const unsigned*)(base);
        qa[kt][1] = *(const unsigned*)(base + 8 * HDIM);
        qa[kt][2] = *(const unsigned*)(base + 8);
        qa[kt][3] = *(const unsigned*)(base + 8 * HDIM + 8);
    }

    const __half* Kp = g_K + (size_t)bh * SS_ * HDIM;
    const __half* Vp = g_V + (size_t)bh * SS_ * HDIM;

    const unsigned sKu = smem_u32(sK), sVu = smem_u32(sV);
    const int crow = tid >> 3, c8 = tid & 7;

    auto load_tile = [&](int buf, int kv0) {
#pragma unroll
        for (int i = 0; i < 2; i++) {
            int row = crow + i * 32;
            unsigned off = (unsigned)(buf * ATILE + row * ASTRIDE + c8 * 8) * 2u;
            CP_ASYNC16(sKu + off, Kp + (size_t)(kv0 + row) * HDIM + c8 * 8);
            CP_ASYNC16(sVu + off, Vp + (size_t)(kv0 + row) * HDIM + c8 * 8);
        }
        CP_COMMIT();
    };

    // per-lane ldmatrix row offsets (bytes)
    const unsigned rowoffK = (unsigned)((lane & 7) * (ASTRIDE * 2)) + ((lane & 8) << 1);
    const unsigned rowoffV = (unsigned)((lane & 15) * (ASTRIDE * 2));

    float o[8][4];
#pragma unroll
    for (int i = 0; i < 8; i++)
#pragma unroll
        for (int j = 0; j < 4; j++) o[i][j] = 0.f;
    float mrun0 = -INFINITY, mrun1 = -INFINITY, l0 = 0.f, l1 = 0.f;

    const unsigned long long* mb64 = (const unsigned long long*)g_mb;
    const size_t mbase = ((size_t)bidx * SS_ + qr) * (SS_ / 64);

    load_tile(0, 0);

    const int NT = SS_ / 64;
    for (int tile = 0; tile < NT; tile++) {
        const int buf = tile & 1;
        if (tile + 1 < NT) {
            load_tile(buf ^ 1, (tile + 1) * 64);
            CP_WAIT(1);
        } else {
            CP_WAIT(0);
        }
        __syncthreads();

        const unsigned kb = sKu + (unsigned)(buf * ATILE * 2) + rowoffK;
        const unsigned vb = sVu + (unsigned)(buf * ATILE * 2) + rowoffV;

        // S = Q K^T
        float sc[8][4];
#pragma unroll
        for (int i = 0; i < 8; i++)
#pragma unroll
            for (int j = 0; j < 4; j++) sc[i][j] = 0.f;
#pragma unroll
        for (int kt = 0; kt < 4; kt++)
#pragma unroll
            for (int ni = 0; ni < 8; ni++) {
                unsigned bk[2];
                ldsm_x2(bk[0], bk[1], kb + (unsigned)(ni * (8 * ASTRIDE * 2) + kt * 32));
                mma16816(sc[ni], qa[kt], bk);
            }

        // scale + mask
        unsigned long long mr0 = mb64[mbase + tile];
        unsigned long long mr1 = mb64[mbase + 8 * (SS_ / 64) + tile];
        float mx0 = -INFINITY, mx1 = -INFINITY;
#pragma unroll
        for (int ni = 0; ni < 8; ni++) {
            int c0 = ni * 8 + 2 * t, c1 = c0 + 1;
            float v0 = sc[ni][0] * 0.125f; if (!((mr0 >> c0) & 1ull)) v0 = -1e9f;
            float v1 = sc[ni][1] * 0.125f; if (!((mr0 >> c1) & 1ull)) v1 = -1e9f;
            float v2 = sc[ni][2] * 0.125f; if (!((mr1 >> c0) & 1ull)) v2 = -1e9f;
            float v3 = sc[ni][3] * 0.125f; if (!((mr1 >> c1) & 1ull)) v3 = -1e9f;
            sc[ni][0] = v0; sc[ni][1] = v1; sc[ni][2] = v2; sc[ni][3] = v3;
            mx0 = fmaxf(mx0, fmaxf(v0, v1));
            mx1 = fmaxf(mx1, fmaxf(v2, v3));
        }
        mx0 = fmaxf(mx0, __shfl_xor_sync(0xffffffffu, mx0, 1));
        mx0 = fmaxf(mx0, __shfl_xor_sync(0xffffffffu, mx0, 2));
        mx1 = fmaxf(mx1, __shfl_xor_sync(0xffffffffu, mx1, 1));
        mx1 = fmaxf(mx1, __shfl_xor_sync(0xffffffffu, mx1, 2));

        float nm0 = fmaxf(mrun0, mx0), nm1 = fmaxf(mrun1, mx1);
        float f0 = __expf(mrun0 - nm0), f1 = __expf(mrun1 - nm1);
        mrun0 = nm0; mrun1 = nm1;

        float sum0 = 0.f, sum1 = 0.f;
        unsigned pa[4][4];
#pragma unroll
        for (int kt = 0; kt < 4; kt++) {
            int jl = 2 * kt, jh = 2 * kt + 1;
            float p00 = __expf(sc[jl][0] - nm0), p01 = __expf(sc[jl][1] - nm0);
            float p02 = __expf(sc[jl][2] - nm1), p03 = __expf(sc[jl][3] - nm1);
            float p10 = __expf(sc[jh][0] - nm0), p11 = __expf(sc[jh][1] - nm0);
            float p12 = __expf(sc[jh][2] - nm1), p13 = __expf(sc[jh][3] - nm1);
            sum0 += p00 + p01 + p10 + p11;
            sum1 += p02 + p03 + p12 + p13;
            pa[kt][0] = pack_h2(p00, p01);
            pa[kt][1] = pack_h2(p02, p03);
            pa[kt][2] = pack_h2(p10, p11);
            pa[kt][3] = pack_h2(p12, p13);
        }
        sum0 += __shfl_xor_sync(0xffffffffu, sum0, 1);
        sum0 += __shfl_xor_sync(0xffffffffu, sum0, 2);
        sum1 += __shfl_xor_sync(0xffffffffu, sum1, 1);
        sum1 += __shfl_xor_sync(0xffffffffu, sum1, 2);
        l0 = l0 * f0 + sum0;
        l1 = l1 * f1 + sum1;

#pragma unroll
        for (int nd = 0; nd < 8; nd++) {
            o[nd][0] *= f0; o[nd][1] *= f0; o[nd][2] *= f1; o[nd][3] *= f1;
        }
        // O += P V  (V fragments via ldmatrix.trans from row-major smem)
#pragma unroll
        for (int kt = 0; kt < 4; kt++)
#pragma unroll
            for (int nd = 0; nd < 8; nd++) {
                unsigned bv[2];
                ldsm_x2_t(bv[0], bv[1],
                          vb + (unsigned)(kt * (16 * ASTRIDE * 2) + nd * 16));
                mma16816(o[nd], pa[kt], bv);
            }
        __syncthreads();
    }

    float inv0 = 1.f / l0, inv1 = 1.f / l1;
    float* Op0 = out + ((size_t)bidx * SS_ + qr) * DD_ + h * HDIM;
    float* Op1 = Op0 + 8 * DD_;
#pragma unroll
    for (int nd = 0; nd < 8; nd++) {
        int d = nd * 8 + 2 * t;
        *(float2*)(Op0 + d) = make_float2(o[nd][0] * inv0, o[nd][1] * inv0);
        *(float2*)(Op1 + d) = make_float2(o[nd][2] * inv1, o[nd][3] * inv1);
    }
}

// ---------------------------------------------------------------------------
extern "C" void kernel_launch(void* const* d_in, const int* in_sizes, int n_in,
                              void* d_out, int out_size) {
    (void)in_sizes; (void)n_in; (void)out_size;
    const float* query = (const float*)d_in[0];
    const float* key   = (const float*)d_in[1];
    const float* value = (const float*)d_in[2];
    const int*   mask  = (const int*)d_in[3];
    const float* Wq = (const float*)d_in[4];
    const float* bq = (const float*)d_in[5];
    const float* Wk = (const float*)d_in[6];
    const float* bk = (const float*)d_in[7];
    const float* Wv = (const float*)d_in[8];
    const float* bv = (const float*)d_in[9];

    const int proj_smem = 4 * PSTAGE * (int)sizeof(float);  // 73728 B
    cudaFuncSetAttribute(proj_kernel, cudaFuncAttributeMaxDynamicSharedMemorySize,
                         proj_smem);

    pack_mask_kernel<<<(BB_ * SS_ * SS_) / 256, 256>>>(mask);

    dim3 gp(DD_ / 128, (BB_ * SS_) / 128, 3);   // (8, 32, 3)
    proj_kernel<<<gp, 256, proj_smem>>>(query, key, value, Wq, Wk, Wv, bq, bk, bv);

    dim3 ga(SS_ / 128, BB_ * HH_);              // (16, 32)
    attn_kernel<<<ga, 256>>>((float*)d_out);
}

// round 3
// speedup vs baseline: 1.6404x; 1.6404x over previous
#include <cuda_runtime.h>
#include <cuda_fp16.h>

#define BB_  2
#define SS_  2048
#define DD_  1024
#define HH_  16
#define HDIM 64

// Scratch
__device__ __align__(16) __half g_Q[(size_t)BB_ * HH_ * SS_ * HDIM];
__device__ __align__(16) __half g_K[(size_t)BB_ * HH_ * SS_ * HDIM];
__device__ __align__(16) __half g_V[(size_t)BB_ * HH_ * SS_ * HDIM];
__device__ __align__(16) __half g_Xh[(size_t)3 * BB_ * SS_ * DD_];   // q,k,v inputs fp16
__device__ __align__(16) __half g_Wh[(size_t)3 * DD_ * DD_];         // Wq,Wk,Wv fp16
__device__ unsigned int g_mb[(size_t)BB_ * SS_ * SS_ / 32];

#define QSCALE 0.1803368801111204f   // 0.125 * log2(e)

// ---------------------------------------------------------------------------
__device__ __forceinline__ void mma16816(float (&c)[4], const unsigned (&a)[4],
                                         const unsigned (&b)[2]) {
    asm volatile(
        "mma.sync.aligned.m16n8k16.row.col.f32.f16.f16.f32 "
        "{%0,%1,%2,%3}, {%4,%5,%6,%7}, {%8,%9}, {%0,%1,%2,%3};\n"
        : "+f"(c[0]), "+f"(c[1]), "+f"(c[2]), "+f"(c[3])
        : "r"(a[0]), "r"(a[1]), "r"(a[2]), "r"(a[3]), "r"(b[0]), "r"(b[1]));
}

__device__ __forceinline__ unsigned pack_h2(float lo, float hi) {
    __half2 h = __floats2half2_rn(lo, hi);
    return *reinterpret_cast<unsigned*>(&h);
}

__device__ __forceinline__ float ex2f(float x) {
    float y;
    asm("ex2.approx.ftz.f32 %0, %1;" : "=f"(y) : "f"(x));
    return y;
}

__device__ __forceinline__ unsigned smem_u32(const void* p) {
    unsigned r;
    asm("{ .reg .u64 t; cvta.to.shared.u64 t, %1; cvt.u32.u64 %0, t; }"
        : "=r"(r) : "l"(p));
    return r;
}

#define CP_ASYNC16(dst, src) \
    asm volatile("cp.async.cg.shared.global [%0], [%1], 16;\n" ::"r"(dst), "l"(src))
#define CP_COMMIT() asm volatile("cp.async.commit_group;\n")
#define CP_WAIT(n)  asm volatile("cp.async.wait_group %0;\n" ::"n"(n))

__device__ __forceinline__ void ldsm_x4(unsigned& r0, unsigned& r1, unsigned& r2,
                                        unsigned& r3, unsigned addr) {
    asm volatile("ldmatrix.sync.aligned.m8n8.x4.shared.b16 {%0,%1,%2,%3}, [%4];"
                 : "=r"(r0), "=r"(r1), "=r"(r2), "=r"(r3) : "r"(addr));
}
__device__ __forceinline__ void ldsm_x2(unsigned& r0, unsigned& r1, unsigned addr) {
    asm volatile("ldmatrix.sync.aligned.m8n8.x2.shared.b16 {%0,%1}, [%2];"
                 : "=r"(r0), "=r"(r1) : "r"(addr));
}
__device__ __forceinline__ void ldsm_x2_t(unsigned& r0, unsigned& r1, unsigned addr) {
    asm volatile("ldmatrix.sync.aligned.m8n8.x2.trans.shared.b16 {%0,%1}, [%2];"
                 : "=r"(r0), "=r"(r1) : "r"(addr));
}

// ---------------------------------------------------------------------------
// Kernel 0: pack mask, vectorized (int4 per thread)
// ---------------------------------------------------------------------------
__global__ void pack_mask_kernel(const int4* __restrict__ mask) {
    int idx = blockIdx.x * 256 + threadIdx.x;
    int4 m = mask[idx];
    unsigned nib = (unsigned)(m.x != 0) | ((unsigned)(m.y != 0) << 1) |
                   ((unsigned)(m.z != 0) << 2) | ((unsigned)(m.w != 0) << 3);
    int lane = threadIdx.x & 31;
    unsigned v = nib << ((lane & 7) * 4);
    v |= __shfl_xor_sync(0xffffffffu, v, 1);
    v |= __shfl_xor_sync(0xffffffffu, v, 2);
    v |= __shfl_xor_sync(0xffffffffu, v, 4);
    if ((lane & 7) == 0) g_mb[idx >> 3] = v;
}

// ---------------------------------------------------------------------------
// Kernel 0b: fp32 -> fp16 bulk convert (float4 -> 2x half2 packed in uint2)
// ---------------------------------------------------------------------------
__global__ void f2h_kernel(const float4* __restrict__ src, uint2* __restrict__ dst) {
    int i = blockIdx.x * 256 + threadIdx.x;
    float4 v = src[i];
    uint2 o;
    o.x = pack_h2(v.x, v.y);
    o.y = pack_h2(v.z, v.w);
    dst[i] = o;
}

// ---------------------------------------------------------------------------
// Kernel 1: fused projection GEMMs (z = 0/1/2 -> Q/K/V), pure fp16 datapath.
// 128x128x64 tiles, 2-stage cp.async, XOR-swizzled smem + ldmatrix.
// Q output pre-scaled by 0.125*log2(e).
// ---------------------------------------------------------------------------
#define PSTG 8192   // halfs per stage per operand (128 rows x 64)

__global__ __launch_bounds__(256) void proj_kernel(const float* const* unused) {
    extern __shared__ __half smemh[];
    __half* sA = smemh;              // [2][8192]
    __half* sB = smemh + 2 * PSTG;   // [2][8192]

    const int z = blockIdx.z;
    const __half* X = g_Xh + (size_t)z * BB_ * SS_ * DD_;
    const __half* W = g_Wh + (size_t)z * DD_ * DD_;
    __half* out = (z == 0) ? g_Q : (z == 1) ? g_K : g_V;
    // bias lives in fp16 W-scratch? No: biases stay fp32 via global pointer table
    // passed through unused; simpler: biases re-read from g (set below via launch args)

    const int tid = threadIdx.x;
    const int warp = tid >> 5, lane = tid & 31;
    const int g = lane >> 2, t = lane & 3;
    const int wm = warp & 1, wn = warp >> 1;
    const int m0 = blockIdx.y * 128, n0 = blockIdx.x * 128;

    const unsigned sAu = smem_u32(sA), sBu = smem_u32(sB);

    auto load_stage = [&](int buf, int kk) {
#pragma unroll
        for (int i = 0; i < 4; i++) {
            int id = tid + i * 256;
            int row = id >> 3, c = id & 7;
            int csw = c ^ (row & 7);
            unsigned doff = (unsigned)(buf * PSTG + row * 64 + csw * 8) * 2u;
            CP_ASYNC16(sAu + doff, X + (size_t)(m0 + row) * DD_ + kk + c * 8);
            CP_ASYNC16(sBu + doff, W + (size_t)(n0 + row) * DD_ + kk + c * 8);
        }
        CP_COMMIT();
    };

    float acc[4][4][4];
#pragma unroll
    for (int mi = 0; mi < 4; mi++)
#pragma unroll
        for (int ni = 0; ni < 4; ni++)
#pragma unroll
            for (int j = 0; j < 4; j++) acc[mi][ni][j] = 0.f;

    // precompute per-lane ldmatrix row/base components
    const int arow = wm * 64 + (lane & 15);          // + mi*16
    const int brow = wn * 32 + (lane & 7);           // + ni*8
    const int ac_hi = (lane >> 4);                   // chunk +0/+1
    const int bc_hi = ((lane >> 3) & 1);

    load_stage(0, 0);

    const int NSTEPS = DD_ / 64;  // 16
    for (int s = 0; s < NSTEPS; s++) {
        if (s + 1 < NSTEPS) {
            load_stage((s + 1) & 1, (s + 1) * 64);
            CP_WAIT(1);
        } else {
            CP_WAIT(0);
        }
        __syncthreads();
        const int buf = s & 1;

#pragma unroll
        for (int k16 = 0; k16 < 4; k16++) {
            unsigned a[4][4], b[4][2];
#pragma unroll
            for (int mi = 0; mi < 4; mi++) {
                int row = arow + mi * 16;
                int c = k16 * 2 + ac_hi;
                unsigned addr = sAu +
                    (unsigned)(buf * PSTG + row * 64 + (c ^ (row & 7)) * 8) * 2u;
                ldsm_x4(a[mi][0], a[mi][1], a[mi][2], a[mi][3], addr);
            }
#pragma unroll
            for (int ni = 0; ni < 4; ni++) {
                int row = brow + ni * 8;
                int c = k16 * 2 + bc_hi;
                unsigned addr = sBu +
                    (unsigned)(buf * PSTG + row * 64 + (c ^ (row & 7)) * 8) * 2u;
                ldsm_x2(b[ni][0], b[ni][1], addr);
            }
#pragma unroll
            for (int mi = 0; mi < 4; mi++)
#pragma unroll
                for (int ni = 0; ni < 4; ni++) mma16816(acc[mi][ni], a[mi], b[ni]);
        }
        __syncthreads();
    }

    // Epilogue: bias (fp32, via __constant__-free global pointer g_bias) + scale
    extern __device__ float g_bias_dummy;  // (not used)
    (void)unused;
    // bias pointers are stored in g_biasptr below
    {
        extern __device__ const float* g_biasptr[3];
        const float* bias = g_biasptr[z];
        const float sc = (z == 0) ? QSCALE : 1.0f;
#pragma unroll
        for (int mi = 0; mi < 4; mi++) {
            int mrow = m0 + wm * 64 + mi * 16 + g;
            int bidx = mrow >> 11;
            int srow = mrow & (SS_ - 1);
#pragma unroll
            for (int ni = 0; ni < 4; ni++) {
                int ncol = n0 + wn * 32 + ni * 8 + 2 * t;
                float b0 = bias[ncol], b1 = bias[ncol + 1];
                int h = ncol >> 6, d = ncol & 63;
                size_t base = (((size_t)(bidx * HH_ + h) * SS_ + srow) * HDIM + d);
                *(__half2*)(out + base) = __floats2half2_rn(
                    (acc[mi][ni][0] + b0) * sc, (acc[mi][ni][1] + b1) * sc);
                *(__half2*)(out + base + 8 * HDIM) = __floats2half2_rn(
                    (acc[mi][ni][2] + b0) * sc, (acc[mi][ni][3] + b1) * sc);
            }
        }
    }
}

__device__ const float* g_biasptr[3];
__global__ void set_biasptr(const float* b0, const float* b1, const float* b2) {
    g_biasptr[0] = b0; g_biasptr[1] = b1; g_biasptr[2] = b2;
}

// ---------------------------------------------------------------------------
// Kernel 2: flash attention. 128 threads (4 warps x 16 Q rows), Q block 64.
// KV tiles 64, 2-stage cp.async, swizzled ldmatrix. exp2-domain softmax
// (Q pre-scaled by 0.125*log2e at projection).
// ---------------------------------------------------------------------------
#define ASTG 4096   // halfs per stage per tensor (64 x 64)

__global__ __launch_bounds__(128, 3) void attn_kernel(float* __restrict__ out) {
    __shared__ __align__(16) __half sK[2][ASTG];
    __shared__ __align__(16) __half sV[2][ASTG];

    const int tid = threadIdx.x;
    const int warp = tid >> 5, lane = tid & 31;
    const int g = lane >> 2, t = lane & 3;

    const int bh = blockIdx.y;
    const int bidx = bh >> 4, h = bh & 15;
    const int q0 = blockIdx.x * 64;
    const int qr = q0 + warp * 16 + g;

    // Q fragments (already scaled by 0.125*log2e)
    const __half* Qp = g_Q + ((size_t)bh * SS_ + q0 + warp * 16) * HDIM;
    unsigned qa[4][4];
#pragma unroll
    for (int kt = 0; kt < 4; kt++) {
        const __half* base = Qp + g * HDIM + kt * 16 + 2 * t;
        qa[kt][0] = *(const unsigned*)(base);
        qa[kt][1] = *(const unsigned*)(base + 8 * HDIM);
        qa[kt][2] = *(const unsigned*)(base + 8);
        qa[kt][3] = *(const unsigned*)(base + 8 * HDIM + 8);
    }

    const __half* Kp = g_K + (size_t)bh * SS_ * HDIM;
    const __half* Vp = g_V + (size_t)bh * SS_ * HDIM;
    const unsigned sKu = smem_u32(sK), sVu = smem_u32(sV);

    auto load_tile = [&](int buf, int kv0) {
#pragma unroll
        for (int i = 0; i < 4; i++) {
            int id = tid + i * 128;
            int row = id >> 3, c = id & 7;
            unsigned doff = (unsigned)(buf * ASTG + row * 64 + (c ^ (row & 7)) * 8) * 2u;
            CP_ASYNC16(sKu + doff, Kp + (size_t)(kv0 + row) * HDIM + c * 8);
            CP_ASYNC16(sVu + doff, Vp + (size_t)(kv0 + row) * HDIM + c * 8);
        }
        CP_COMMIT();
    };

    const int krow_l = lane & 7, kc_hi = (lane >> 3) & 1;
    const int vrow_l = lane & 15;

    float o[8][4];
#pragma unroll
    for (int i = 0; i < 8; i++)
#pragma unroll
        for (int j = 0; j < 4; j++) o[i][j] = 0.f;
    float mrun0 = -INFINITY, mrun1 = -INFINITY, l0 = 0.f, l1 = 0.f;

    const unsigned long long* mb64 = (const unsigned long long*)g_mb;
    const size_t mbase = ((size_t)bidx * SS_ + qr) * (SS_ / 64);

    load_tile(0, 0);

    const int NT = SS_ / 64;
    for (int tile = 0; tile < NT; tile++) {
        const int buf = tile & 1;
        if (tile + 1 < NT) {
            load_tile(buf ^ 1, (tile + 1) * 64);
            CP_WAIT(1);
        } else {
            CP_WAIT(0);
        }
        __syncthreads();

        // S = Q K^T  (scores already in exp2 domain)
        float sc[8][4];
#pragma unroll
        for (int i = 0; i < 8; i++)
#pragma unroll
            for (int j = 0; j < 4; j++) sc[i][j] = 0.f;
#pragma unroll
        for (int kt = 0; kt < 4; kt++)
#pragma unroll
            for (int ni = 0; ni < 8; ni++) {
                int row = ni * 8 + krow_l;
                int c = kt * 2 + kc_hi;
                unsigned addr = sKu +
                    (unsigned)(buf * ASTG + row * 64 + (c ^ (row & 7)) * 8) * 2u;
                unsigned bk[2];
                ldsm_x2(bk[0], bk[1], addr);
                mma16816(sc[ni], qa[kt], bk);
            }

        // mask (masked -> -1e9) + row max
        unsigned long long mr0 = mb64[mbase + tile];
        unsigned long long mr1 = mb64[mbase + 8 * (SS_ / 64) + tile];
        float mx0 = -INFINITY, mx1 = -INFINITY;
#pragma unroll
        for (int ni = 0; ni < 8; ni++) {
            int c0 = ni * 8 + 2 * t, c1 = c0 + 1;
            float v0 = ((mr0 >> c0) & 1ull) ? sc[ni][0] : -1e9f;
            float v1 = ((mr0 >> c1) & 1ull) ? sc[ni][1] : -1e9f;
            float v2 = ((mr1 >> c0) & 1ull) ? sc[ni][2] : -1e9f;
            float v3 = ((mr1 >> c1) & 1ull) ? sc[ni][3] : -1e9f;
            sc[ni][0] = v0; sc[ni][1] = v1; sc[ni][2] = v2; sc[ni][3] = v3;
            mx0 = fmaxf(mx0, fmaxf(v0, v1));
            mx1 = fmaxf(mx1, fmaxf(v2, v3));
        }
        mx0 = fmaxf(mx0, __shfl_xor_sync(0xffffffffu, mx0, 1));
        mx0 = fmaxf(mx0, __shfl_xor_sync(0xffffffffu, mx0, 2));
        mx1 = fmaxf(mx1, __shfl_xor_sync(0xffffffffu, mx1, 1));
        mx1 = fmaxf(mx1, __shfl_xor_sync(0xffffffffu, mx1, 2));

        float nm0 = fmaxf(mrun0, mx0), nm1 = fmaxf(mrun1, mx1);
        float f0 = ex2f(mrun0 - nm0), f1 = ex2f(mrun1 - nm1);
        mrun0 = nm0; mrun1 = nm1;

        float sum0 = 0.f, sum1 = 0.f;
        unsigned pa[4][4];
#pragma unroll
        for (int kt = 0; kt < 4; kt++) {
            int jl = 2 * kt, jh = 2 * kt + 1;
            float p00 = ex2f(sc[jl][0] - nm0), p01 = ex2f(sc[jl][1] - nm0);
            float p02 = ex2f(sc[jl][2] - nm1), p03 = ex2f(sc[jl][3] - nm1);
            float p10 = ex2f(sc[jh][0] - nm0), p11 = ex2f(sc[jh][1] - nm0);
            float p12 = ex2f(sc[jh][2] - nm1), p13 = ex2f(sc[jh][3] - nm1);
            sum0 += p00 + p01 + p10 + p11;
            sum1 += p02 + p03 + p12 + p13;
            pa[kt][0] = pack_h2(p00, p01);
            pa[kt][1] = pack_h2(p02, p03);
            pa[kt][2] = pack_h2(p10, p11);
            pa[kt][3] = pack_h2(p12, p13);
        }
        sum0 += __shfl_xor_sync(0xffffffffu, sum0, 1);
        sum0 += __shfl_xor_sync(0xffffffffu, sum0, 2);
        sum1 += __shfl_xor_sync(0xffffffffu, sum1, 1);
        sum1 += __shfl_xor_sync(0xffffffffu, sum1, 2);
        l0 = l0 * f0 + sum0;
        l1 = l1 * f1 + sum1;

#pragma unroll
        for (int nd = 0; nd < 8; nd++) {
            o[nd][0] *= f0; o[nd][1] *= f0; o[nd][2] *= f1; o[nd][3] *= f1;
        }
        // O += P V  (V via ldmatrix.trans from row-major swizzled smem)
#pragma unroll
        for (int kt = 0; kt < 4; kt++) {
            int row = kt * 16 + vrow_l;
#pragma unroll
            for (int nd = 0; nd < 8; nd++) {
                unsigned addr = sVu +
                    (unsigned)(buf * ASTG + row * 64 + ((nd ^ (row & 7)) * 8)) * 2u;
                unsigned bv[2];
                ldsm_x2_t(bv[0], bv[1], addr);
                mma16816(o[nd], pa[kt], bv);
            }
        }
        __syncthreads();
    }

    float inv0 = 1.f / l0, inv1 = 1.f / l1;
    float* Op0 = out + ((size_t)bidx * SS_ + qr) * DD_ + h * HDIM;
    float* Op1 = Op0 + 8 * DD_;
#pragma unroll
    for (int nd = 0; nd < 8; nd++) {
        int d = nd * 8 + 2 * t;
        *(float2*)(Op0 + d) = make_float2(o[nd][0] * inv0, o[nd][1] * inv0);
        *(float2*)(Op1 + d) = make_float2(o[nd][2] * inv1, o[nd][3] * inv1);
    }
}

// ---------------------------------------------------------------------------
extern "C" void kernel_launch(void* const* d_in, const int* in_sizes, int n_in,
                              void* d_out, int out_size) {
    (void)in_sizes; (void)n_in; (void)out_size;
    const float* query = (const float*)d_in[0];
    const float* key   = (const float*)d_in[1];
    const float* value = (const float*)d_in[2];
    const int*   mask  = (const int*)d_in[3];
    const float* Wq = (const float*)d_in[4];
    const float* bq = (const float*)d_in[5];
    const float* Wk = (const float*)d_in[6];
    const float* bk = (const float*)d_in[7];
    const float* Wv = (const float*)d_in[8];
    const float* bv = (const float*)d_in[9];

    set_biasptr<<<1, 1>>>(bq, bk, bv);
    pack_mask_kernel<<<(BB_ * SS_ * SS_) / 1024, 256>>>((const int4*)mask);

    // fp32 -> fp16 converts
    __half* xh;  cudaGetSymbolAddress((void**)&xh, g_Xh);
    __half* wh;  cudaGetSymbolAddress((void**)&wh, g_Wh);
    const int NX4 = BB_ * SS_ * DD_ / 4;   // 1048576
    const int NW4 = DD_ * DD_ / 4;         // 262144
    f2h_kernel<<<NX4 / 256, 256>>>((const float4*)query, (uint2*)xh);
    f2h_kernel<<<NX4 / 256, 256>>>((const float4*)key,   (uint2*)(xh + (size_t)BB_ * SS_ * DD_));
    f2h_kernel<<<NX4 / 256, 256>>>((const float4*)value, (uint2*)(xh + (size_t)2 * BB_ * SS_ * DD_));
    f2h_kernel<<<NW4 / 256, 256>>>((const float4*)Wq, (uint2*)wh);
    f2h_kernel<<<NW4 / 256, 256>>>((const float4*)Wk, (uint2*)(wh + (size_t)DD_ * DD_));
    f2h_kernel<<<NW4 / 256, 256>>>((const float4*)Wv, (uint2*)(wh + (size_t)2 * DD_ * DD_));

    const int proj_smem = 4 * PSTG * (int)sizeof(__half);  // 65536 B
    cudaFuncSetAttribute(proj_kernel, cudaFuncAttributeMaxDynamicSharedMemorySize,
                         proj_smem);
    dim3 gp(DD_ / 128, (BB_ * SS_) / 128, 3);   // (8, 32, 3)
    proj_kernel<<<gp, 256, proj_smem>>>(nullptr);

    dim3 ga(SS_ / 64, BB_ * HH_);               // (32, 32)
    attn_kernel<<<ga, 128>>>((float*)d_out);
}

// round 4
// speedup vs baseline: 1.9001x; 1.1583x over previous
#include <cuda_runtime.h>
#include <cuda_fp16.h>

#define BB_  2
#define SS_  2048
#define DD_  1024
#define HH_  16
#define HDIM 64

// Scratch
__device__ __align__(16) __half g_Q[(size_t)BB_ * HH_ * SS_ * HDIM];
__device__ __align__(16) __half g_K[(size_t)BB_ * HH_ * SS_ * HDIM];
__device__ __align__(16) __half g_V[(size_t)BB_ * HH_ * SS_ * HDIM];
__device__ __align__(16) __half g_Xh[(size_t)3 * BB_ * SS_ * DD_];
__device__ __align__(16) __half g_Wh[(size_t)3 * DD_ * DD_];
__device__ unsigned int g_mb[(size_t)BB_ * SS_ * SS_ / 32];
__device__ const float* g_biasptr[3];

#define QSCALE 0.1803368801111204f   // 0.125 * log2(e)
#define NEGH   (-65504.0f)           // most negative finite half
#define ONESH2 0x3C003C00u           // half2(1,1)

// ---------------------------------------------------------------------------
__device__ __forceinline__ void mma16816(float (&c)[4], const unsigned (&a)[4],
                                         const unsigned (&b)[2]) {
    asm volatile(
        "mma.sync.aligned.m16n8k16.row.col.f32.f16.f16.f32 "
        "{%0,%1,%2,%3}, {%4,%5,%6,%7}, {%8,%9}, {%0,%1,%2,%3};\n"
        : "+f"(c[0]), "+f"(c[1]), "+f"(c[2]), "+f"(c[3])
        : "r"(a[0]), "r"(a[1]), "r"(a[2]), "r"(a[3]), "r"(b[0]), "r"(b[1]));
}

__device__ __forceinline__ unsigned pack_h2(float lo, float hi) {
    __half2 h = __floats2half2_rn(lo, hi);
    return *reinterpret_cast<unsigned*>(&h);
}
__device__ __forceinline__ __half2 u2h(unsigned u) {
    return *reinterpret_cast<__half2*>(&u);
}
__device__ __forceinline__ unsigned h2u(__half2 h) {
    return *reinterpret_cast<unsigned*>(&h);
}
__device__ __forceinline__ unsigned ex2_h2(unsigned a) {
    unsigned d;
    asm("ex2.approx.f16x2 %0, %1;" : "=r"(d) : "r"(a));
    return d;
}
__device__ __forceinline__ float ex2f(float x) {
    float y;
    asm("ex2.approx.ftz.f32 %0, %1;" : "=f"(y) : "f"(x));
    return y;
}
__device__ __forceinline__ unsigned smem_u32(const void* p) {
    unsigned r;
    asm("{ .reg .u64 t; cvta.to.shared.u64 t, %1; cvt.u32.u64 %0, t; }"
        : "=r"(r) : "l"(p));
    return r;
}

#define CP_ASYNC16(dst, src) \
    asm volatile("cp.async.cg.shared.global [%0], [%1], 16;\n" ::"r"(dst), "l"(src))
#define CP_COMMIT() asm volatile("cp.async.commit_group;\n")
#define CP_WAIT(n)  asm volatile("cp.async.wait_group %0;\n" ::"n"(n))

__device__ __forceinline__ void ldsm_x4(unsigned& r0, unsigned& r1, unsigned& r2,
                                        unsigned& r3, unsigned addr) {
    asm volatile("ldmatrix.sync.aligned.m8n8.x4.shared.b16 {%0,%1,%2,%3}, [%4];"
                 : "=r"(r0), "=r"(r1), "=r"(r2), "=r"(r3) : "r"(addr));
}
__device__ __forceinline__ void ldsm_x4_t(unsigned& r0, unsigned& r1, unsigned& r2,
                                          unsigned& r3, unsigned addr) {
    asm volatile("ldmatrix.sync.aligned.m8n8.x4.trans.shared.b16 {%0,%1,%2,%3}, [%4];"
                 : "=r"(r0), "=r"(r1), "=r"(r2), "=r"(r3) : "r"(addr));
}

// ---------------------------------------------------------------------------
// pack mask (int4 per thread -> bit per element)
// ---------------------------------------------------------------------------
__global__ void pack_mask_kernel(const int4* __restrict__ mask) {
    int idx = blockIdx.x * 256 + threadIdx.x;
    int4 m = mask[idx];
    unsigned nib = (unsigned)(m.x != 0) | ((unsigned)(m.y != 0) << 1) |
                   ((unsigned)(m.z != 0) << 2) | ((unsigned)(m.w != 0) << 3);
    int lane = threadIdx.x & 31;
    unsigned v = nib << ((lane & 7) * 4);
    v |= __shfl_xor_sync(0xffffffffu, v, 1);
    v |= __shfl_xor_sync(0xffffffffu, v, 2);
    v |= __shfl_xor_sync(0xffffffffu, v, 4);
    if ((lane & 7) == 0) g_mb[idx >> 3] = v;
}

// ---------------------------------------------------------------------------
// fp32 -> fp16 bulk converts, batched: y selects the tensor
// ---------------------------------------------------------------------------
__global__ void f2h_x_kernel(const float4* __restrict__ a, const float4* __restrict__ b,
                             const float4* __restrict__ c) {
    const float4* src = (blockIdx.y == 0) ? a : (blockIdx.y == 1) ? b : c;
    uint2* dst = (uint2*)g_Xh + (size_t)blockIdx.y * (BB_ * SS_ * DD_ / 4);
    int i = blockIdx.x * 256 + threadIdx.x;
    float4 v = src[i];
    dst[i] = make_uint2(pack_h2(v.x, v.y), pack_h2(v.z, v.w));
}
__global__ void f2h_w_kernel(const float4* __restrict__ a, const float4* __restrict__ b,
                             const float4* __restrict__ c) {
    const float4* src = (blockIdx.y == 0) ? a : (blockIdx.y == 1) ? b : c;
    uint2* dst = (uint2*)g_Wh + (size_t)blockIdx.y * (DD_ * DD_ / 4);
    int i = blockIdx.x * 256 + threadIdx.x;
    float4 v = src[i];
    dst[i] = make_uint2(pack_h2(v.x, v.y), pack_h2(v.z, v.w));
}
__global__ void set_biasptr(const float* b0, const float* b1, const float* b2) {
    g_biasptr[0] = b0; g_biasptr[1] = b1; g_biasptr[2] = b2;
}

// ---------------------------------------------------------------------------
// fused projection GEMMs (z=0/1/2 -> Q/K/V), fp16 datapath, 128x128x64 tiles.
// Q pre-scaled by 0.125*log2(e).
// ---------------------------------------------------------------------------
#define PSTG 8192

__global__ __launch_bounds__(256, 2) void proj_kernel() {
    extern __shared__ __half smemh[];
    __half* sA = smemh;
    __half* sB = smemh + 2 * PSTG;

    const int z = blockIdx.z;
    const __half* X = g_Xh + (size_t)z * BB_ * SS_ * DD_;
    const __half* W = g_Wh + (size_t)z * DD_ * DD_;
    __half* out = (z == 0) ? g_Q : (z == 1) ? g_K : g_V;

    const int tid = threadIdx.x;
    const int warp = tid >> 5, lane = tid & 31;
    const int g = lane >> 2, t = lane & 3;
    const int wm = warp & 1, wn = warp >> 1;
    const int m0 = blockIdx.y * 128, n0 = blockIdx.x * 128;

    const unsigned sAu = smem_u32(sA), sBu = smem_u32(sB);

    auto load_stage = [&](int buf, int kk) {
#pragma unroll
        for (int i = 0; i < 4; i++) {
            int id = tid + i * 256;
            int row = id >> 3, c = id & 7;
            unsigned doff = (unsigned)(buf * PSTG + row * 64 + (c ^ (row & 7)) * 8) * 2u;
            CP_ASYNC16(sAu + doff, X + (size_t)(m0 + row) * DD_ + kk + c * 8);
            CP_ASYNC16(sBu + doff, W + (size_t)(n0 + row) * DD_ + kk + c * 8);
        }
        CP_COMMIT();
    };

    float acc[4][4][4];
#pragma unroll
    for (int mi = 0; mi < 4; mi++)
#pragma unroll
        for (int ni = 0; ni < 4; ni++)
#pragma unroll
            for (int j = 0; j < 4; j++) acc[mi][ni][j] = 0.f;

    const int arow = wm * 64 + (lane & 15);
    const int ac_hi = (lane >> 4);
    const int brow = wn * 32 + ((lane >> 4) & 1) * 8 + (lane & 7);
    const int bc_hi = (lane >> 3) & 1;

    load_stage(0, 0);

    const int NSTEPS = DD_ / 64;
    for (int s = 0; s < NSTEPS; s++) {
        if (s + 1 < NSTEPS) {
            load_stage((s + 1) & 1, (s + 1) * 64);
            CP_WAIT(1);
        } else {
            CP_WAIT(0);
        }
        __syncthreads();
        const int buf = s & 1;

#pragma unroll
        for (int k16 = 0; k16 < 4; k16++) {
            unsigned a[4][4], b[4][2];
#pragma unroll
            for (int mi = 0; mi < 4; mi++) {
                int row = arow + mi * 16;
                int c = k16 * 2 + ac_hi;
                unsigned addr = sAu +
                    (unsigned)(buf * PSTG + row * 64 + (c ^ (row & 7)) * 8) * 2u;
                ldsm_x4(a[mi][0], a[mi][1], a[mi][2], a[mi][3], addr);
            }
#pragma unroll
            for (int ni2 = 0; ni2 < 2; ni2++) {
                int row = brow + ni2 * 16;
                int c = k16 * 2 + bc_hi;
                unsigned addr = sBu +
                    (unsigned)(buf * PSTG + row * 64 + (c ^ (row & 7)) * 8) * 2u;
                ldsm_x4(b[2 * ni2][0], b[2 * ni2][1], b[2 * ni2 + 1][0],
                        b[2 * ni2 + 1][1], addr);
            }
#pragma unroll
            for (int mi = 0; mi < 4; mi++)
#pragma unroll
                for (int ni = 0; ni < 4; ni++) mma16816(acc[mi][ni], a[mi], b[ni]);
        }
        __syncthreads();
    }

    const float* bias = g_biasptr[z];
    const float sc = (z == 0) ? QSCALE : 1.0f;
#pragma unroll
    for (int mi = 0; mi < 4; mi++) {
        int mrow = m0 + wm * 64 + mi * 16 + g;
        int bidx = mrow >> 11;
        int srow = mrow & (SS_ - 1);
#pragma unroll
        for (int ni = 0; ni < 4; ni++) {
            int ncol = n0 + wn * 32 + ni * 8 + 2 * t;
            float b0 = bias[ncol], b1 = bias[ncol + 1];
            int h = ncol >> 6, d = ncol & 63;
            size_t base = (((size_t)(bidx * HH_ + h) * SS_ + srow) * HDIM + d);
            *(__half2*)(out + base) = __floats2half2_rn(
                (acc[mi][ni][0] + b0) * sc, (acc[mi][ni][1] + b1) * sc);
            *(__half2*)(out + base + 8 * HDIM) = __floats2half2_rn(
                (acc[mi][ni][2] + b0) * sc, (acc[mi][ni][3] + b1) * sc);
        }
    }
}

// ---------------------------------------------------------------------------
// flash attention: 128 threads (4 warps x 16 Q rows), KV tiles 64, half2
// softmax in exp2 domain, row sums via ones-mma.
// ---------------------------------------------------------------------------
#define ASTG 4096

__global__ __launch_bounds__(128, 3) void attn_kernel(float* __restrict__ out) {
    __shared__ __align__(16) __half sK[2][ASTG];
    __shared__ __align__(16) __half sV[2][ASTG];

    const int tid = threadIdx.x;
    const int warp = tid >> 5, lane = tid & 31;
    const int g = lane >> 2, t = lane & 3;

    const int bh = blockIdx.y;
    const int bidx = bh >> 4, h = bh & 15;
    const int q0 = blockIdx.x * 64;
    const int qr = q0 + warp * 16 + g;

    const __half* Qp = g_Q + ((size_t)bh * SS_ + q0 + warp * 16) * HDIM;
    unsigned qa[4][4];
#pragma unroll
    for (int kt = 0; kt < 4; kt++) {
        const __half* base = Qp + g * HDIM + kt * 16 + 2 * t;
        qa[kt][0] = *(const unsigned*)(base);
        qa[kt][1] = *(const unsigned*)(base + 8 * HDIM);
        qa[kt][2] = *(const unsigned*)(base + 8);
        qa[kt][3] = *(const unsigned*)(base + 8 * HDIM + 8);
    }

    const __half* Kp = g_K + (size_t)bh * SS_ * HDIM;
    const __half* Vp = g_V + (size_t)bh * SS_ * HDIM;
    const unsigned sKu = smem_u32(sK), sVu = smem_u32(sV);

    auto load_tile = [&](int buf, int kv0) {
#pragma unroll
        for (int i = 0; i < 4; i++) {
            int id = tid + i * 128;
            int row = id >> 3, c = id & 7;
            unsigned doff = (unsigned)(buf * ASTG + row * 64 + (c ^ (row & 7)) * 8) * 2u;
            CP_ASYNC16(sKu + doff, Kp + (size_t)(kv0 + row) * HDIM + c * 8);
            CP_ASYNC16(sVu + doff, Vp + (size_t)(kv0 + row) * HDIM + c * 8);
        }
        CP_COMMIT();
    };

    const int klo = ((lane >> 4) & 1) * 8 + (lane & 7);   // K row within 16-block
    const int kc_hi = (lane >> 3) & 1;
    const int vrow_l = lane & 15;
    const int vc_hi = (lane >> 4) & 1;

    float o[8][4];
#pragma unroll
    for (int i = 0; i < 8; i++)
#pragma unroll
        for (int j = 0; j < 4; j++) o[i][j] = 0.f;
    float mrun0 = -INFINITY, mrun1 = -INFINITY, l0 = 0.f, l1 = 0.f;

    const unsigned long long* mb64 = (const unsigned long long*)g_mb;
    const size_t mbase = ((size_t)bidx * SS_ + qr) * (SS_ / 64);

    load_tile(0, 0);

    const int NT = SS_ / 64;
    for (int tile = 0; tile < NT; tile++) {
        const int buf = tile & 1;
        if (tile + 1 < NT) {
            load_tile(buf ^ 1, (tile + 1) * 64);
            CP_WAIT(1);
        } else {
            CP_WAIT(0);
        }
        __syncthreads();

        // S = Q K^T  (exp2 domain; ldmatrix.x4 K loads)
        float sc[8][4];
#pragma unroll
        for (int i = 0; i < 8; i++)
#pragma unroll
            for (int j = 0; j < 4; j++) sc[i][j] = 0.f;
#pragma unroll
        for (int kt = 0; kt < 4; kt++)
#pragma unroll
            for (int ni2 = 0; ni2 < 4; ni2++) {
                int row = ni2 * 16 + klo;
                int c = kt * 2 + kc_hi;
                unsigned addr = sKu +
                    (unsigned)(buf * ASTG + row * 64 + (c ^ (row & 7)) * 8) * 2u;
                unsigned k0, k1, k2, k3;
                ldsm_x4(k0, k1, k2, k3, addr);
                { unsigned b2[2] = {k0, k1}; mma16816(sc[2 * ni2], qa[kt], b2); }
                { unsigned b2[2] = {k2, k3}; mma16816(sc[2 * ni2 + 1], qa[kt], b2); }
            }

        // mask select (f32) -> pack to half2
        unsigned long long mr0 = mb64[mbase + tile];
        unsigned long long mr1 = mb64[mbase + 8 * (SS_ / 64) + tile];
        unsigned h01[8], h23[8];
#pragma unroll
        for (int ni = 0; ni < 8; ni++) {
            int c0 = ni * 8 + 2 * t, c1 = c0 + 1;
            float v0 = ((mr0 >> c0) & 1ull) ? sc[ni][0] : NEGH;
            float v1 = ((mr0 >> c1) & 1ull) ? sc[ni][1] : NEGH;
            float v2 = ((mr1 >> c0) & 1ull) ? sc[ni][2] : NEGH;
            float v3 = ((mr1 >> c1) & 1ull) ? sc[ni][3] : NEGH;
            h01[ni] = pack_h2(v0, v1);
            h23[ni] = pack_h2(v2, v3);
        }

        // row max via HMAX2 chains
        __half2 hm0 = u2h(h01[0]), hm1 = u2h(h23[0]);
#pragma unroll
        for (int ni = 1; ni < 8; ni++) {
            hm0 = __hmax2(hm0, u2h(h01[ni]));
            hm1 = __hmax2(hm1, u2h(h23[ni]));
        }
        float mx0 = __half2float(__hmax(__low2half(hm0), __high2half(hm0)));
        float mx1 = __half2float(__hmax(__low2half(hm1), __high2half(hm1)));
        mx0 = fmaxf(mx0, __shfl_xor_sync(0xffffffffu, mx0, 1));
        mx0 = fmaxf(mx0, __shfl_xor_sync(0xffffffffu, mx0, 2));
        mx1 = fmaxf(mx1, __shfl_xor_sync(0xffffffffu, mx1, 1));
        mx1 = fmaxf(mx1, __shfl_xor_sync(0xffffffffu, mx1, 2));

        float nm0 = fmaxf(mrun0, mx0), nm1 = fmaxf(mrun1, mx1);
        float f0 = ex2f(mrun0 - nm0), f1 = ex2f(mrun1 - nm1);
        mrun0 = nm0; mrun1 = nm1;

        // P = exp2(S - nm) in half2 (fragments land in mma-A layout)
        const __half2 nmh0 = __float2half2_rn(nm0);
        const __half2 nmh1 = __float2half2_rn(nm1);
        unsigned p01[8], p23[8];
#pragma unroll
        for (int ni = 0; ni < 8; ni++) {
            p01[ni] = ex2_h2(h2u(__hsub2(u2h(h01[ni]), nmh0)));
            p23[ni] = ex2_h2(h2u(__hsub2(u2h(h23[ni]), nmh1)));
        }

        // row sums via ones-mma (exact f32, no shuffles)
        float lacc[4] = {0.f, 0.f, 0.f, 0.f};
        const unsigned ones[2] = {ONESH2, ONESH2};
#pragma unroll
        for (int kt = 0; kt < 4; kt++) {
            unsigned a[4] = {p01[2 * kt], p23[2 * kt], p01[2 * kt + 1], p23[2 * kt + 1]};
            mma16816(lacc, a, ones);
        }
        l0 = l0 * f0 + lacc[0];
        l1 = l1 * f1 + lacc[2];

#pragma unroll
        for (int nd = 0; nd < 8; nd++) {
            o[nd][0] *= f0; o[nd][1] *= f0; o[nd][2] *= f1; o[nd][3] *= f1;
        }
        // O += P V  (ldmatrix.x4.trans V loads)
#pragma unroll
        for (int kt = 0; kt < 4; kt++) {
            unsigned a[4] = {p01[2 * kt], p23[2 * kt], p01[2 * kt + 1], p23[2 * kt + 1]};
            int row = kt * 16 + vrow_l;
#pragma unroll
            for (int nd2 = 0; nd2 < 4; nd2++) {
                int colblk = nd2 * 2 + vc_hi;
                unsigned addr = sVu +
                    (unsigned)(buf * ASTG + row * 64 + ((colblk ^ (row & 7)) * 8)) * 2u;
                unsigned v0, v1, v2, v3;
                ldsm_x4_t(v0, v1, v2, v3, addr);
                { unsigned b2[2] = {v0, v1}; mma16816(o[2 * nd2], a, b2); }
                { unsigned b2[2] = {v2, v3}; mma16816(o[2 * nd2 + 1], a, b2); }
            }
        }
        __syncthreads();
    }

    float inv0 = 1.f / l0, inv1 = 1.f / l1;
    float* Op0 = out + ((size_t)bidx * SS_ + qr) * DD_ + h * HDIM;
    float* Op1 = Op0 + 8 * DD_;
#pragma unroll
    for (int nd = 0; nd < 8; nd++) {
        int d = nd * 8 + 2 * t;
        *(float2*)(Op0 + d) = make_float2(o[nd][0] * inv0, o[nd][1] * inv0);
        *(float2*)(Op1 + d) = make_float2(o[nd][2] * inv1, o[nd][3] * inv1);
    }
}

// ---------------------------------------------------------------------------
extern "C" void kernel_launch(void* const* d_in, const int* in_sizes, int n_in,
                              void* d_out, int out_size) {
    (void)in_sizes; (void)n_in; (void)out_size;
    const float* query = (const float*)d_in[0];
    const float* key   = (const float*)d_in[1];
    const float* value = (const float*)d_in[2];
    const int*   mask  = (const int*)d_in[3];
    const float* Wq = (const float*)d_in[4];
    const float* bq = (const float*)d_in[5];
    const float* Wk = (const float*)d_in[6];
    const float* bk = (const float*)d_in[7];
    const float* Wv = (const float*)d_in[8];
    const float* bv = (const float*)d_in[9];

    set_biasptr<<<1, 1>>>(bq, bk, bv);
    pack_mask_kernel<<<(BB_ * SS_ * SS_) / 1024, 256>>>((const int4*)mask);

    dim3 gx(BB_ * SS_ * DD_ / 4 / 256, 3);
    f2h_x_kernel<<<gx, 256>>>((const float4*)query, (const float4*)key,
                              (const float4*)value);
    dim3 gw(DD_ * DD_ / 4 / 256, 3);
    f2h_w_kernel<<<gw, 256>>>((const float4*)Wq, (const float4*)Wk,
                              (const float4*)Wv);

    const int proj_smem = 4 * PSTG * (int)sizeof(__half);  // 65536 B
    cudaFuncSetAttribute(proj_kernel, cudaFuncAttributeMaxDynamicSharedMemorySize,
                         proj_smem);
    dim3 gp(DD_ / 128, (BB_ * SS_) / 128, 3);
    proj_kernel<<<gp, 256, proj_smem>>>();

    dim3 ga(SS_ / 64, BB_ * HH_);
    attn_kernel<<<ga, 128>>>((float*)d_out);
}